// round 8
// baseline (speedup 1.0000x reference)
#include <cuda_runtime.h>
#include <cuda_fp16.h>
#include <cstdint>

// Problem constants
#define BATCH   16384
#define MAXF    32
#define NFEAT   768
#define FT_OUT  1024
#define FULL_MASK 0xFFFFFFFFu

// Slice config
#define NSLICE      8
#define SLICE_COLS  128                               // fp16 -> 256 B per row-slice
#define SBLOCKS     18
#define GRID_MAIN   (NSLICE * SBLOCKS)                // 144 CTAs (one wave)
#define SPB         ((BATCH + SBLOCKS - 1) / SBLOCKS) // 911 samples per block

#define TAB_BYTES   (NFEAT * SLICE_COLS * 2)          // 196608 B = 192 KB
#define SMEM_MAIN   (TAB_BYTES + 3 * SLICE_COLS * 4)  // + ftb/owS/owN = 198144 B

// Device globals
__device__ __half g_ftw_h[NFEAT * FT_OUT];   // fp16 table
__device__ uint2  g_meta[BATCH * MAXF];      // {idxS | idxN<<16, val bits}
__device__ float  g_part[BATCH * NSLICE];    // per-(sample,slice) partials

// ---------------------------------------------------------------------------
// helpers
// ---------------------------------------------------------------------------
__device__ __forceinline__ uint32_t smem_u32(const void* p) {
    uint32_t a;
    asm("{ .reg .u64 t; cvta.to.shared.u64 t, %1; cvt.u32.u64 %0, t; }" : "=r"(a) : "l"(p));
    return a;
}
__device__ __forceinline__ void cp_async16(uint32_t dst, const void* src) {
    asm volatile("cp.async.cg.shared.global [%0], [%1], 16;"
                 :: "r"(dst), "l"(src) : "memory");
}

// ---------------------------------------------------------------------------
// Kernel 1: ft_w fp32 -> fp16 (one float4 per thread)
// ---------------------------------------------------------------------------
__global__ void convert_ftw_kernel(const float* __restrict__ ftw) {
    int i = blockIdx.x * blockDim.x + threadIdx.x;
    float4 v = reinterpret_cast<const float4*>(ftw)[i];
    __half2* dst = reinterpret_cast<__half2*>(g_ftw_h);
    dst[2 * i + 0] = __floats2half2_rn(v.x, v.y);
    dst[2 * i + 1] = __floats2half2_rn(v.z, v.w);
}

// ---------------------------------------------------------------------------
// Kernel 2: pack per-(sample,feature) metadata
// ---------------------------------------------------------------------------
__global__ void pack_meta_kernel(const float* __restrict__ values,
                                 const int*   __restrict__ stm,
                                 const int*   __restrict__ nstm) {
    int i = blockIdx.x * 256 + threadIdx.x;      // i < BATCH*MAXF
    g_meta[i] = make_uint2((unsigned)stm[i] | ((unsigned)nstm[i] << 16),
                           __float_as_uint(values[i]));
}

// ---------------------------------------------------------------------------
// Kernel 3: main — smem-resident 128-col table slice, warp-per-sample.
// Per feature per warp: 2x LDS.64 (conflict-free) + 0.5x uniform LDG.128 meta
// + 4x HFMA2. No L1 misses on table data.
// ---------------------------------------------------------------------------
__global__ void __launch_bounds__(512, 1)
nnue_main_kernel(const float* __restrict__ ft_b, const float* __restrict__ out_w)
{
    extern __shared__ char smem[];
    __half* s_tab = reinterpret_cast<__half*>(smem);
    float*  s_ftb = reinterpret_cast<float*>(smem + TAB_BYTES);
    float*  s_owS = s_ftb + SLICE_COLS;
    float*  s_owN = s_owS + SLICE_COLS;

    const int tid  = threadIdx.x;
    const int w    = tid >> 5;
    const int lane = tid & 31;
    const int slice  = blockIdx.x & (NSLICE - 1);
    const int sblock = blockIdx.x >> 3;
    const int c0 = slice * SLICE_COLS;

    // Stage table slice: 768 rows x 256 B via cp.async (24 x 16B per thread)
    {
        const char* src = reinterpret_cast<const char*>(g_ftw_h) + c0 * 2;
        uint32_t dst = smem_u32(s_tab);
        #pragma unroll
        for (int j = 0; j < 24; ++j) {
            int c = tid + 512 * j;                 // 0..12287
            int row = c >> 4, inner = (c & 15) * 16;
            cp_async16(dst + row * 256 + inner,
                       src + (size_t)row * (FT_OUT * 2) + inner);
        }
        asm volatile("cp.async.commit_group;" ::: "memory");
    }
    if (tid < SLICE_COLS) {
        s_ftb[tid] = ft_b[c0 + tid];
        s_owS[tid] = out_w[c0 + tid];
        s_owN[tid] = out_w[FT_OUT + c0 + tid];
    }
    asm volatile("cp.async.wait_group 0;" ::: "memory");
    __syncthreads();

    const int sstart = sblock * SPB;
    const int send   = min(BATCH, sstart + SPB);
    const char* tabc = reinterpret_cast<const char*>(s_tab);
    const int laneoff = lane * 8;

    for (int s = sstart + w; s < send; s += 16) {
        const uint4* mp = reinterpret_cast<const uint4*>(g_meta + s * MAXF);

        __half2 aS0 = __half2half2(__float2half_rn(0.0f));
        __half2 aS1 = aS0, aN0 = aS0, aN1 = aS0;

        #pragma unroll 4
        for (int c = 0; c < 16; ++c) {              // 2 features per iteration
            uint4 m = __ldg(mp + c);                // uniform LDG.128 broadcast
            {
                const uint2* rS = reinterpret_cast<const uint2*>(
                    tabc + ((m.x & 0xFFFFu) << 8) + laneoff);
                const uint2* rN = reinterpret_cast<const uint2*>(
                    tabc + ((m.x >> 16) << 8) + laneoff);
                __half2 v2 = __float2half2_rn(__uint_as_float(m.y));
                uint2 ds = *rS, dn = *rN;
                aS0 = __hfma2(v2, *reinterpret_cast<__half2*>(&ds.x), aS0);
                aS1 = __hfma2(v2, *reinterpret_cast<__half2*>(&ds.y), aS1);
                aN0 = __hfma2(v2, *reinterpret_cast<__half2*>(&dn.x), aN0);
                aN1 = __hfma2(v2, *reinterpret_cast<__half2*>(&dn.y), aN1);
            }
            {
                const uint2* rS = reinterpret_cast<const uint2*>(
                    tabc + ((m.z & 0xFFFFu) << 8) + laneoff);
                const uint2* rN = reinterpret_cast<const uint2*>(
                    tabc + ((m.z >> 16) << 8) + laneoff);
                __half2 v2 = __float2half2_rn(__uint_as_float(m.w));
                uint2 ds = *rS, dn = *rN;
                aS0 = __hfma2(v2, *reinterpret_cast<__half2*>(&ds.x), aS0);
                aS1 = __hfma2(v2, *reinterpret_cast<__half2*>(&ds.y), aS1);
                aN0 = __hfma2(v2, *reinterpret_cast<__half2*>(&dn.x), aN0);
                aN1 = __hfma2(v2, *reinterpret_cast<__half2*>(&dn.y), aN1);
            }
        }

        // Epilogue: lane owns cols c0 + lane*4 .. +3 (both sides)
        float4 bb = reinterpret_cast<const float4*>(s_ftb)[lane];
        float4 wS = reinterpret_cast<const float4*>(s_owS)[lane];
        float4 wN = reinterpret_cast<const float4*>(s_owN)[lane];
        float2 p0 = __half22float2(aS0), p1 = __half22float2(aS1);
        float2 q0 = __half22float2(aN0), q1 = __half22float2(aN1);
        float partial = 0.0f, hh;
        hh = fminf(fmaxf(p0.x + bb.x, 0.f), 1.f); partial = fmaf(hh, wS.x, partial);
        hh = fminf(fmaxf(p0.y + bb.y, 0.f), 1.f); partial = fmaf(hh, wS.y, partial);
        hh = fminf(fmaxf(p1.x + bb.z, 0.f), 1.f); partial = fmaf(hh, wS.z, partial);
        hh = fminf(fmaxf(p1.y + bb.w, 0.f), 1.f); partial = fmaf(hh, wS.w, partial);
        hh = fminf(fmaxf(q0.x + bb.x, 0.f), 1.f); partial = fmaf(hh, wN.x, partial);
        hh = fminf(fmaxf(q0.y + bb.y, 0.f), 1.f); partial = fmaf(hh, wN.y, partial);
        hh = fminf(fmaxf(q1.x + bb.z, 0.f), 1.f); partial = fmaf(hh, wN.z, partial);
        hh = fminf(fmaxf(q1.y + bb.w, 0.f), 1.f); partial = fmaf(hh, wN.w, partial);

        #pragma unroll
        for (int off = 16; off > 0; off >>= 1)
            partial += __shfl_xor_sync(FULL_MASK, partial, off);

        if (lane == 0) g_part[s * NSLICE + slice] = partial;   // deterministic
    }
}

// ---------------------------------------------------------------------------
// Kernel 4: sum 8 slice-partials + sigmoid
// ---------------------------------------------------------------------------
__global__ void final_kernel(const float* __restrict__ out_b,
                             float* __restrict__ out) {
    int b = blockIdx.x * 256 + threadIdx.x;
    const float4* p = reinterpret_cast<const float4*>(g_part + b * NSLICE);
    float4 a = p[0], c = p[1];
    float x = ((a.x + a.y) + (a.z + a.w)) + ((c.x + c.y) + (c.z + c.w)) + out_b[0];
    out[b] = 1.0f / (1.0f + __expf(-x));
}

// ---------------------------------------------------------------------------
// kernel_launch
// Inputs: values, stm_indices, nstm_indices, ft_w, ft_b, out_w, out_b
// ---------------------------------------------------------------------------
extern "C" void kernel_launch(void* const* d_in, const int* in_sizes, int n_in,
                              void* d_out, int out_size)
{
    const float* values   = (const float*)d_in[0];
    const int*   stm_idx  = (const int*)  d_in[1];
    const int*   nstm_idx = (const int*)  d_in[2];
    const float* ft_w     = (const float*)d_in[3];
    const float* ft_b     = (const float*)d_in[4];
    const float* out_w    = (const float*)d_in[5];
    const float* out_b    = (const float*)d_in[6];
    float*       out      = (float*)d_out;

    static bool attr_set = false;
    if (!attr_set) {
        cudaFuncSetAttribute(nnue_main_kernel,
                             cudaFuncAttributeMaxDynamicSharedMemorySize, SMEM_MAIN);
        attr_set = true;
    }

    convert_ftw_kernel<<<(NFEAT * FT_OUT / 4) / 256, 256>>>(ft_w);
    pack_meta_kernel<<<(BATCH * MAXF) / 256, 256>>>(values, stm_idx, nstm_idx);
    nnue_main_kernel<<<GRID_MAIN, 512, SMEM_MAIN>>>(ft_b, out_w);
    final_kernel<<<BATCH / 256, 256>>>(out_b, out);
}

// round 9
// speedup vs baseline: 1.2262x; 1.2262x over previous
#include <cuda_runtime.h>
#include <cuda_fp16.h>
#include <cstdint>

// Problem constants
#define BATCH   16384
#define MAXF    32
#define NFEAT   768
#define FT_OUT  1024
#define FULL_MASK 0xFFFFFFFFu

// fp16 copy of ft_w, rebuilt every kernel_launch (deterministic).
__device__ __half g_ftw_h[NFEAT * FT_OUT];

// ---------------------------------------------------------------------------
// Kernel 1: ft_w fp32 -> fp16 (one float4 per thread)
// ---------------------------------------------------------------------------
__global__ void convert_ftw_kernel(const float* __restrict__ ftw) {
    int i = blockIdx.x * blockDim.x + threadIdx.x;
    float4 v = reinterpret_cast<const float4*>(ftw)[i];
    __half2* dst = reinterpret_cast<__half2*>(g_ftw_h);
    dst[2 * i + 0] = __floats2half2_rn(v.x, v.y);
    dst[2 * i + 1] = __floats2half2_rn(v.z, v.w);
}

// ---------------------------------------------------------------------------
// Kernel 2: TWO warps per sample (512 cols each), 4 samples per CTA.
// Meta staged in smem once; 1 uniform LDS.128 per 2 features per warp.
// Inner iteration: 2 features, ALL 8 LDG.128 issued before FMAs (MLP=8).
// ---------------------------------------------------------------------------
__global__ void __launch_bounds__(256, 4)
nnue_main_kernel(const float* __restrict__ values,
                 const int*   __restrict__ stm_idx,
                 const int*   __restrict__ nstm_idx,
                 const float* __restrict__ ft_b,
                 const float* __restrict__ out_w,
                 const float* __restrict__ out_b,
                 float*       __restrict__ out)
{
    __shared__ uint2 s_meta[4][MAXF];   // [sampleInCta][feature] = {idxS|idxN<<16, valbits}
    __shared__ float s_partial[8];

    const int tid       = threadIdx.x;
    const int warpInCta = tid >> 5;
    const int lane      = tid & 31;
    const int sInCta    = warpInCta >> 1;     // 4 samples per CTA
    const int h         = warpInCta & 1;      // column half: 0 or 1
    const int b         = blockIdx.x * 4 + sInCta;

    // Stage metadata: threads 0..127 each handle one (sample, feature)
    if (tid < 128) {
        const int s = tid >> 5;
        const int f = tid & 31;
        const int bg = blockIdx.x * 4 + s;
        const int is = stm_idx [bg * MAXF + f];
        const int in = nstm_idx[bg * MAXF + f];
        const float v = values [bg * MAXF + f];
        s_meta[s][f] = make_uint2((unsigned)is | ((unsigned)in << 16),
                                  __float_as_uint(v));
    }
    __syncthreads();

    // Warp owns cols [h*512, h*512+512). Lane's chunks: +lane*16 B and +512 B.
    const char* Wq = reinterpret_cast<const char*>(g_ftw_h) + h * 1024 + lane * 16;
    const uint4* meta4 = reinterpret_cast<const uint4*>(s_meta[sInCta]);  // 2 feats/uint4

    __half2 accS[8], accN[8];
    #pragma unroll
    for (int i = 0; i < 8; ++i) {
        accS[i] = __half2half2(__float2half_rn(0.0f));
        accN[i] = accS[i];
    }

    #pragma unroll 4
    for (int c = 0; c < 16; ++c) {              // 2 features per iteration
        const uint4 m = meta4[c];               // uniform LDS.128 broadcast

        const char* rS0 = Wq + (size_t)(m.x & 0xFFFFu) * (FT_OUT * 2);
        const char* rN0 = Wq + (size_t)(m.x >> 16)     * (FT_OUT * 2);
        const char* rS1 = Wq + (size_t)(m.z & 0xFFFFu) * (FT_OUT * 2);
        const char* rN1 = Wq + (size_t)(m.z >> 16)     * (FT_OUT * 2);

        // Issue all 8 independent LDG.128 first (MLP = 8)
        uint4 s0a = *reinterpret_cast<const uint4*>(rS0);
        uint4 s0b = *reinterpret_cast<const uint4*>(rS0 + 512);
        uint4 n0a = *reinterpret_cast<const uint4*>(rN0);
        uint4 n0b = *reinterpret_cast<const uint4*>(rN0 + 512);
        uint4 s1a = *reinterpret_cast<const uint4*>(rS1);
        uint4 s1b = *reinterpret_cast<const uint4*>(rS1 + 512);
        uint4 n1a = *reinterpret_cast<const uint4*>(rN1);
        uint4 n1b = *reinterpret_cast<const uint4*>(rN1 + 512);

        const __half2 v0 = __float2half2_rn(__uint_as_float(m.y));
        const __half2 v1 = __float2half2_rn(__uint_as_float(m.w));

        accS[0] = __hfma2(v0, *reinterpret_cast<__half2*>(&s0a.x), accS[0]);
        accS[1] = __hfma2(v0, *reinterpret_cast<__half2*>(&s0a.y), accS[1]);
        accS[2] = __hfma2(v0, *reinterpret_cast<__half2*>(&s0a.z), accS[2]);
        accS[3] = __hfma2(v0, *reinterpret_cast<__half2*>(&s0a.w), accS[3]);
        accS[4] = __hfma2(v0, *reinterpret_cast<__half2*>(&s0b.x), accS[4]);
        accS[5] = __hfma2(v0, *reinterpret_cast<__half2*>(&s0b.y), accS[5]);
        accS[6] = __hfma2(v0, *reinterpret_cast<__half2*>(&s0b.z), accS[6]);
        accS[7] = __hfma2(v0, *reinterpret_cast<__half2*>(&s0b.w), accS[7]);
        accN[0] = __hfma2(v0, *reinterpret_cast<__half2*>(&n0a.x), accN[0]);
        accN[1] = __hfma2(v0, *reinterpret_cast<__half2*>(&n0a.y), accN[1]);
        accN[2] = __hfma2(v0, *reinterpret_cast<__half2*>(&n0a.z), accN[2]);
        accN[3] = __hfma2(v0, *reinterpret_cast<__half2*>(&n0a.w), accN[3]);
        accN[4] = __hfma2(v0, *reinterpret_cast<__half2*>(&n0b.x), accN[4]);
        accN[5] = __hfma2(v0, *reinterpret_cast<__half2*>(&n0b.y), accN[5]);
        accN[6] = __hfma2(v0, *reinterpret_cast<__half2*>(&n0b.z), accN[6]);
        accN[7] = __hfma2(v0, *reinterpret_cast<__half2*>(&n0b.w), accN[7]);

        accS[0] = __hfma2(v1, *reinterpret_cast<__half2*>(&s1a.x), accS[0]);
        accS[1] = __hfma2(v1, *reinterpret_cast<__half2*>(&s1a.y), accS[1]);
        accS[2] = __hfma2(v1, *reinterpret_cast<__half2*>(&s1a.z), accS[2]);
        accS[3] = __hfma2(v1, *reinterpret_cast<__half2*>(&s1a.w), accS[3]);
        accS[4] = __hfma2(v1, *reinterpret_cast<__half2*>(&s1b.x), accS[4]);
        accS[5] = __hfma2(v1, *reinterpret_cast<__half2*>(&s1b.y), accS[5]);
        accS[6] = __hfma2(v1, *reinterpret_cast<__half2*>(&s1b.z), accS[6]);
        accS[7] = __hfma2(v1, *reinterpret_cast<__half2*>(&s1b.w), accS[7]);
        accN[0] = __hfma2(v1, *reinterpret_cast<__half2*>(&n1a.x), accN[0]);
        accN[1] = __hfma2(v1, *reinterpret_cast<__half2*>(&n1a.y), accN[1]);
        accN[2] = __hfma2(v1, *reinterpret_cast<__half2*>(&n1a.z), accN[2]);
        accN[3] = __hfma2(v1, *reinterpret_cast<__half2*>(&n1a.w), accN[3]);
        accN[4] = __hfma2(v1, *reinterpret_cast<__half2*>(&n1b.x), accN[4]);
        accN[5] = __hfma2(v1, *reinterpret_cast<__half2*>(&n1b.y), accN[5]);
        accN[6] = __hfma2(v1, *reinterpret_cast<__half2*>(&n1b.z), accN[6]);
        accN[7] = __hfma2(v1, *reinterpret_cast<__half2*>(&n1b.w), accN[7]);
    }

    // ----- epilogue: fp32 bias add, clip [0,1], dot with out_w -----
    // Lane cols: u in {0,1}: col0 = h*512 + u*256 + lane*8
    //   -> float4 index fidx = h*128 + u*64 + lane*2 + {0,1}
    const float4* fb4 = reinterpret_cast<const float4*>(ft_b);
    const float4* ow4 = reinterpret_cast<const float4*>(out_w);

    float partial = 0.0f;
    #pragma unroll
    for (int u = 0; u < 2; ++u) {
        const int fidx = h * 128 + u * 64 + lane * 2;
        float4 b0 = fb4[fidx + 0];
        float4 b1 = fb4[fidx + 1];
        #pragma unroll
        for (int side = 0; side < 2; ++side) {
            const __half2* acc = (side == 0) ? &accS[u*4] : &accN[u*4];
            const int owb = side * 256 + fidx;
            float4 w0 = ow4[owb + 0];
            float4 w1 = ow4[owb + 1];
            float2 p0 = __half22float2(acc[0]);
            float2 p1 = __half22float2(acc[1]);
            float2 p2 = __half22float2(acc[2]);
            float2 p3 = __half22float2(acc[3]);
            float hh;
            hh = fminf(fmaxf(p0.x + b0.x, 0.f), 1.f); partial = fmaf(hh, w0.x, partial);
            hh = fminf(fmaxf(p0.y + b0.y, 0.f), 1.f); partial = fmaf(hh, w0.y, partial);
            hh = fminf(fmaxf(p1.x + b0.z, 0.f), 1.f); partial = fmaf(hh, w0.z, partial);
            hh = fminf(fmaxf(p1.y + b0.w, 0.f), 1.f); partial = fmaf(hh, w0.w, partial);
            hh = fminf(fmaxf(p2.x + b1.x, 0.f), 1.f); partial = fmaf(hh, w1.x, partial);
            hh = fminf(fmaxf(p2.y + b1.y, 0.f), 1.f); partial = fmaf(hh, w1.y, partial);
            hh = fminf(fmaxf(p3.x + b1.z, 0.f), 1.f); partial = fmaf(hh, w1.z, partial);
            hh = fminf(fmaxf(p3.y + b1.w, 0.f), 1.f); partial = fmaf(hh, w1.w, partial);
        }
    }

    // warp reduce
    #pragma unroll
    for (int off = 16; off > 0; off >>= 1)
        partial += __shfl_xor_sync(FULL_MASK, partial, off);

    if (lane == 0) s_partial[warpInCta] = partial;
    __syncthreads();

    // half-0 warp of each sample finalizes
    if (h == 0 && lane == 0) {
        float x = s_partial[warpInCta] + s_partial[warpInCta + 1] + out_b[0];
        out[b] = 1.0f / (1.0f + __expf(-x));
    }
}

// ---------------------------------------------------------------------------
// kernel_launch
// Inputs: values, stm_indices, nstm_indices, ft_w, ft_b, out_w, out_b
// ---------------------------------------------------------------------------
extern "C" void kernel_launch(void* const* d_in, const int* in_sizes, int n_in,
                              void* d_out, int out_size)
{
    const float* values   = (const float*)d_in[0];
    const int*   stm_idx  = (const int*)  d_in[1];
    const int*   nstm_idx = (const int*)  d_in[2];
    const float* ft_w     = (const float*)d_in[3];
    const float* ft_b     = (const float*)d_in[4];
    const float* out_w    = (const float*)d_in[5];
    const float* out_b    = (const float*)d_in[6];
    float*       out      = (float*)d_out;

    convert_ftw_kernel<<<(NFEAT * FT_OUT / 4) / 256, 256>>>(ft_w);
    // 4 samples per CTA -> 4096 CTAs
    nnue_main_kernel<<<BATCH / 4, 256>>>(values, stm_idx, nstm_idx,
                                         ft_b, out_w, out_b, out);
}